// round 7
// baseline (speedup 1.0000x reference)
#include <cuda_runtime.h>
#include <cstddef>

// ProdLayer forward: element_mars[nids] = node_mars[cids].sum(axis=1)
//   d_in[0] node_mars     float32  [N_SRC, 128]
//   d_in[1] element_mars  float32  [N_PROD+1, 128]
//   d_in[2] nids          int32    [N_PROD]
//   d_in[3] cids          int32    [N_PROD, 4]
// Output: float32 [N_PROD+1, 128]
//
// R7: persistent grid-stride. Grid = 148 SMs x 4 blocks (one wave, fully
// resident) and each warp loops over product pairs with a grid-wide stride.
// Eliminates the ~10-25 wave transitions of the flat launch, whose ragged
// tails (front-batched MLP=8 -> high per-CTA spread) left DRAM ~14% idle.
// Per-iteration body identical to R6: 8 front-batched LDG.128 gathers,
// __ldcs index reads, __stcs streaming output stores.

static constexpr int B_F4    = 32;   // 128 floats / 4 per row
static constexpr int SMS     = 148;
static constexpr int BLK_PER_SM = 4;
static constexpr int THREADS = 256;  // 8 warps/block

__device__ __forceinline__ void do_one(
    const float4* __restrict__ node_mars,
    const int*    __restrict__ nids,
    const int4*   __restrict__ cids,
    float4*       __restrict__ out,
    int p, int lane)
{
    const int4 c = __ldcs(&cids[p]);
    const float4 a = __ldg(&node_mars[(size_t)c.x * B_F4 + lane]);
    const float4 b = __ldg(&node_mars[(size_t)c.y * B_F4 + lane]);
    const float4 d = __ldg(&node_mars[(size_t)c.z * B_F4 + lane]);
    const float4 e = __ldg(&node_mars[(size_t)c.w * B_F4 + lane]);
    float4 s;
    s.x = (a.x + b.x) + (d.x + e.x);
    s.y = (a.y + b.y) + (d.y + e.y);
    s.z = (a.z + b.z) + (d.z + e.z);
    s.w = (a.w + b.w) + (d.w + e.w);
    const int o = __ldcs(&nids[p]);
    __stcs(&out[(size_t)o * B_F4 + lane], s);
}

__global__ void __launch_bounds__(THREADS) prodlayer_kernel(
    const float4* __restrict__ node_mars,
    const float4* __restrict__ element_mars,
    const int*    __restrict__ nids,
    const int4*   __restrict__ cids,
    float4*       __restrict__ out,
    int n_prod)
{
    const int warps_total = (int)(gridDim.x * (THREADS / 32));
    const int gwarp = (int)((blockIdx.x * (unsigned)THREADS + threadIdx.x) >> 5);
    const int lane  = threadIdx.x & 31;
    const int stride = warps_total * 2;

    // Full pairs: every iteration of this loop has both products valid.
    const int n_pairs_full = n_prod & ~1;  // even floor
    for (int p0 = gwarp * 2; p0 < n_pairs_full; p0 += stride) {
        const int p1 = p0 + 1;

        const int4 c0 = __ldcs(&cids[p0]);
        const int4 c1 = __ldcs(&cids[p1]);

        const float4 a0 = __ldg(&node_mars[(size_t)c0.x * B_F4 + lane]);
        const float4 b0 = __ldg(&node_mars[(size_t)c0.y * B_F4 + lane]);
        const float4 d0 = __ldg(&node_mars[(size_t)c0.z * B_F4 + lane]);
        const float4 e0 = __ldg(&node_mars[(size_t)c0.w * B_F4 + lane]);
        const float4 a1 = __ldg(&node_mars[(size_t)c1.x * B_F4 + lane]);
        const float4 b1 = __ldg(&node_mars[(size_t)c1.y * B_F4 + lane]);
        const float4 d1 = __ldg(&node_mars[(size_t)c1.z * B_F4 + lane]);
        const float4 e1 = __ldg(&node_mars[(size_t)c1.w * B_F4 + lane]);

        float4 s0, s1;
        s0.x = (a0.x + b0.x) + (d0.x + e0.x);
        s0.y = (a0.y + b0.y) + (d0.y + e0.y);
        s0.z = (a0.z + b0.z) + (d0.z + e0.z);
        s0.w = (a0.w + b0.w) + (d0.w + e0.w);
        s1.x = (a1.x + b1.x) + (d1.x + e1.x);
        s1.y = (a1.y + b1.y) + (d1.y + e1.y);
        s1.z = (a1.z + b1.z) + (d1.z + e1.z);
        s1.w = (a1.w + b1.w) + (d1.w + e1.w);

        const int o0 = __ldcs(&nids[p0]);
        const int o1 = __ldcs(&nids[p1]);
        __stcs(&out[(size_t)o0 * B_F4 + lane], s0);
        __stcs(&out[(size_t)o1 * B_F4 + lane], s1);
    }

    // Tail: odd leftover product (if n_prod is odd) handled by warp 0,
    // reserved row 0 copy handled by warp 1 (d_out is poisoned).
    if (gwarp == 0 && (n_prod & 1)) {
        do_one(node_mars, nids, cids, out, n_prod - 1, lane);
    }
    if (gwarp == 1) {
        __stcs(&out[lane], __ldg(&element_mars[lane]));
    }
}

extern "C" void kernel_launch(void* const* d_in, const int* in_sizes, int n_in,
                              void* d_out, int out_size)
{
    const float4* node_mars    = (const float4*)d_in[0];
    const float4* element_mars = (const float4*)d_in[1];
    const int*    nids         = (const int*)d_in[2];
    const int4*   cids         = (const int4*)d_in[3];
    float4*       out          = (float4*)d_out;

    const int n_prod = in_sizes[2];          // 500000
    const int blocks = SMS * BLK_PER_SM;     // one fully-resident wave

    prodlayer_kernel<<<blocks, THREADS>>>(node_mars, element_mars, nids, cids,
                                          out, n_prod);
}

// round 8
// speedup vs baseline: 1.0197x; 1.0197x over previous
#include <cuda_runtime.h>
#include <cstddef>

// ProdLayer forward: element_mars[nids] = node_mars[cids].sum(axis=1)
//   d_in[0] node_mars     float32  [N_SRC, 128]
//   d_in[1] element_mars  float32  [N_PROD+1, 128]
//   d_in[2] nids          int32    [N_PROD]
//   d_in[3] cids          int32    [N_PROD, 4]
// Output: float32 [N_PROD+1, 128]
//
// R8: persistent grid-stride at FULL residency. R7 failed because
// 4 blk/SM capped occupancy at 50% and DRAM util tracks resident warps.
// Now: __launch_bounds__(256, 8) caps regs at 32 -> 64 warps/SM, grid =
// 148*8 = 1184 blocks, one wave, zero wave transitions. Body is R2's
// light 1-product-per-warp form (4 gathers, ~28 regs): R2 vs R6 showed
// MLP 4 vs 8 is irrelevant at high residency.
// __ldcs index reads, __stcs streaming output stores, __ldg gathers.

static constexpr int B_F4    = 32;   // 128 floats / 4 per row
static constexpr int SMS     = 148;
static constexpr int BLK_PER_SM = 8;
static constexpr int THREADS = 256;  // 8 warps/block

__global__ void __launch_bounds__(THREADS, BLK_PER_SM) prodlayer_kernel(
    const float4* __restrict__ node_mars,
    const float4* __restrict__ element_mars,
    const int*    __restrict__ nids,
    const int4*   __restrict__ cids,
    float4*       __restrict__ out,
    int n_prod)
{
    const int warps_total = (int)(gridDim.x * (THREADS / 32));
    const int gwarp = (int)((blockIdx.x * (unsigned)THREADS + threadIdx.x) >> 5);
    const int lane  = threadIdx.x & 31;

    for (int p = gwarp; p < n_prod; p += warps_total) {
        const int4 c = __ldcs(&cids[p]);

        const float4 a = __ldg(&node_mars[(size_t)c.x * B_F4 + lane]);
        const float4 b = __ldg(&node_mars[(size_t)c.y * B_F4 + lane]);
        const float4 d = __ldg(&node_mars[(size_t)c.z * B_F4 + lane]);
        const float4 e = __ldg(&node_mars[(size_t)c.w * B_F4 + lane]);

        float4 s;
        s.x = (a.x + b.x) + (d.x + e.x);
        s.y = (a.y + b.y) + (d.y + e.y);
        s.z = (a.z + b.z) + (d.z + e.z);
        s.w = (a.w + b.w) + (d.w + e.w);

        const int o = __ldcs(&nids[p]);
        __stcs(&out[(size_t)o * B_F4 + lane], s);
    }

    // Reserved row 0 copy (d_out is poisoned -> row 0 must be written).
    if (gwarp == 0) {
        __stcs(&out[lane], __ldg(&element_mars[lane]));
    }
}

extern "C" void kernel_launch(void* const* d_in, const int* in_sizes, int n_in,
                              void* d_out, int out_size)
{
    const float4* node_mars    = (const float4*)d_in[0];
    const float4* element_mars = (const float4*)d_in[1];
    const int*    nids         = (const int*)d_in[2];
    const int4*   cids         = (const int4*)d_in[3];
    float4*       out          = (float4*)d_out;

    const int n_prod = in_sizes[2];          // 500000
    const int blocks = SMS * BLK_PER_SM;     // 1184 blocks, one resident wave

    prodlayer_kernel<<<blocks, THREADS>>>(node_mars, element_mars, nids, cids,
                                          out, n_prod);
}

// round 9
// speedup vs baseline: 1.0822x; 1.0612x over previous
#include <cuda_runtime.h>
#include <cstddef>

// ProdLayer forward: element_mars[nids] = node_mars[cids].sum(axis=1)
//   d_in[0] node_mars     float32  [N_SRC, 128]
//   d_in[1] element_mars  float32  [N_PROD+1, 128]
//   d_in[2] nids          int32    [N_PROD]
//   d_in[3] cids          int32    [N_PROD, 4]
// Output: float32 [N_PROD+1, 128]
//
// R9: final micro-tune of the flat-launch winner (R2). Findings locked in:
//  - flat beats persistent (CTA replacement = free pipelining; grid-stride
//    loops serialize per-warp load batches): R7/R8 both regressed.
//  - L2 hit rate is pinned at the 126MB/512MB capacity ratio; no policy or
//    tiling beats it (R3/R5 falsified). Traffic fixed at ~1.13 GB.
//  - MLP 4 vs 8 per warp: no difference at high residency (R6).
// Change here: 128-thread CTAs (4 warps) instead of 256 -> 2x finer CTA
// replacement granularity, smoother DRAM issue stream and tail balance.
// Body: warp-per-product, float4 lanes, __ldg gathers, __ldcs indices,
// __stcs streaming stores. Row 0 (reserved, d_out poisoned) handled by an
// extra warp slot.

static constexpr int B_F4    = 32;   // 128 floats / 4 per row
static constexpr int THREADS = 128;  // 4 warps per block

__global__ void __launch_bounds__(THREADS) prodlayer_kernel(
    const float4* __restrict__ node_mars,
    const float4* __restrict__ element_mars,
    const int*    __restrict__ nids,
    const int4*   __restrict__ cids,
    float4*       __restrict__ out,
    int n_prod)
{
    const int gwarp = (int)((blockIdx.x * (unsigned)THREADS + threadIdx.x) >> 5);
    const int lane  = threadIdx.x & 31;

    if (gwarp < n_prod) {
        const int4 c = __ldcs(&cids[gwarp]);

        const float4 a = __ldg(&node_mars[(size_t)c.x * B_F4 + lane]);
        const float4 b = __ldg(&node_mars[(size_t)c.y * B_F4 + lane]);
        const float4 d = __ldg(&node_mars[(size_t)c.z * B_F4 + lane]);
        const float4 e = __ldg(&node_mars[(size_t)c.w * B_F4 + lane]);

        float4 s;
        s.x = (a.x + b.x) + (d.x + e.x);
        s.y = (a.y + b.y) + (d.y + e.y);
        s.z = (a.z + b.z) + (d.z + e.z);
        s.w = (a.w + b.w) + (d.w + e.w);

        const int o = __ldcs(&nids[gwarp]);
        __stcs(&out[(size_t)o * B_F4 + lane], s);
    } else if (gwarp == n_prod) {
        // Reserved row 0: out row 0 = element_mars row 0 (d_out poisoned).
        __stcs(&out[lane], __ldg(&element_mars[lane]));
    }
}

extern "C" void kernel_launch(void* const* d_in, const int* in_sizes, int n_in,
                              void* d_out, int out_size)
{
    const float4* node_mars    = (const float4*)d_in[0];
    const float4* element_mars = (const float4*)d_in[1];
    const int*    nids         = (const int*)d_in[2];
    const int4*   cids         = (const int4*)d_in[3];
    float4*       out          = (float4*)d_out;

    const int n_prod  = in_sizes[2];             // 500000
    const int n_warps = n_prod + 1;              // +1 warp for reserved row 0
    const int blocks  = (n_warps + 3) / 4;       // 4 warps per block

    prodlayer_kernel<<<blocks, THREADS>>>(node_mars, element_mars, nids, cids,
                                          out, n_prod);
}